// round 14
// baseline (speedup 1.0000x reference)
#include <cuda_runtime.h>
#include <cuda_fp16.h>
#include <cstdint>

// ---------------- problem constants ----------------
#define L_Q   13343
#define BLMAX 26686
#define CDIM  256

__constant__ int c_HW[5]    = {100, 50, 25, 13, 7};
__constant__ int c_start[5] = {0, 10000, 12500, 13125, 13294};

// ---------------- scratch (static device globals; no allocs) ----------------
__device__ float    g_oa   [(size_t)BLMAX * 480];   // offsets(320) | logits(160)
__device__ float    g_src2 [(size_t)BLMAX * 256];
__device__ float    g_x    [(size_t)BLMAX * 256];
__device__ float    g_y    [(size_t)BLMAX * 256];
// fp16 activations (half2 words)
__device__ uint32_t g_src16 [(size_t)BLMAX * 128];
__device__ uint32_t g_q16   [(size_t)BLMAX * 128];
__device__ uint32_t g_val16 [(size_t)BLMAX * 128];
__device__ uint32_t g_acc16 [(size_t)BLMAX * 128];
__device__ uint32_t g_x16   [(size_t)BLMAX * 128];
__device__ uint32_t g_h16   [(size_t)BLMAX * 1024];
// fp16 weights, n-major pair-interleaved: WpT[n][kp] = half2(W[2kp][n], W[2kp+1][n])
__device__ uint32_t g_wvp   [256 * 128];
__device__ uint32_t g_woap  [480 * 128];            // rows: wo n=0..319, wa n=320..479
__device__ uint32_t g_woutp [256 * 128];
__device__ uint32_t g_w1p   [2048 * 128];
__device__ uint32_t g_w2p   [256 * 1024];
__device__ float    g_boa   [480];                  // bo | ba

// ---------------- ptx helpers ----------------
__device__ __forceinline__ uint32_t s2u(const void* p) {
    uint32_t a;
    asm("{ .reg .u64 t; cvta.to.shared.u64 t, %1; cvt.u32.u64 %0, t; }" : "=r"(a) : "l"(p));
    return a;
}
__device__ __forceinline__ void cp16(uint32_t s, const void* g) {
    asm volatile("cp.async.cg.shared.global [%0], [%1], 16;\n" :: "r"(s), "l"(g));
}
__device__ __forceinline__ void cp16z(uint32_t s, const void* g, uint32_t bytes) {
    asm volatile("cp.async.cg.shared.global [%0], [%1], 16, %2;\n"
                 :: "r"(s), "l"(g), "r"(bytes));
}
__device__ __forceinline__ void cpcommit() { asm volatile("cp.async.commit_group;\n" ::: "memory"); }
template<int N> __device__ __forceinline__ void cpwait() {
    asm volatile("cp.async.wait_group %0;\n" :: "n"(N) : "memory");
}
__device__ __forceinline__ void mma_f16(float* d, const uint32_t* a, const uint32_t* b) {
    asm volatile(
        "mma.sync.aligned.m16n8k16.row.col.f32.f16.f16.f32 "
        "{%0,%1,%2,%3}, {%4,%5,%6,%7}, {%8,%9}, {%0,%1,%2,%3};\n"
        : "+f"(d[0]), "+f"(d[1]), "+f"(d[2]), "+f"(d[3])
        : "r"(a[0]), "r"(a[1]), "r"(a[2]), "r"(a[3]), "r"(b[0]), "r"(b[1]));
}
#define LDSM4(r0, r1, r2, r3, a) \
    asm volatile("ldmatrix.sync.aligned.m8n8.x4.shared.b16 {%0,%1,%2,%3}, [%4];" \
                 : "=r"(r0), "=r"(r1), "=r"(r2), "=r"(r3) : "r"(a))
__device__ __forceinline__ uint32_t packh2(float lo, float hi) {
    __half2 h = __floats2half2_rn(lo, hi);
    return *(uint32_t*)&h;
}

// ---------------- cp.async pipelined FP16 GEMM (ldmatrix fragments) ----------------
// C[M][N] = act(A16[M][K] @ W + bias); weights n-major WpT[N][K/2] (half2 rows).
// 128x128 block tile, BK=32 halves (16 kpairs), 4 stages, 256 thr = 8 warps (2x4),
// warp 64x32, m16n8k16. Both smem tiles: 128 rows x 16 kpairs, stride 20 u32 (80B)
// -> conflict-free ldmatrix (8-row bank footprint covers all 32 banks).
#define KPC 16
#define TSTRU 20
#define T_STB (128 * TSTRU * 4)             // 10240
#define NSTG  4
#define SMEM_GEMM (NSTG * 2 * T_STB)        // 81920

template<bool RELU, bool OUT_HALF>
__global__ __launch_bounds__(256, 2)
void gemm_h(const __half* __restrict__ A16, const uint32_t* __restrict__ WpT,
            const float* __restrict__ bias, void* __restrict__ Craw,
            int M, int N, int K)
{
    extern __shared__ uint32_t smem[];
    const uint32_t sbA = s2u(smem);
    const uint32_t sbB = sbA + NSTG * T_STB;

    const int tid  = threadIdx.x;
    const int lane = tid & 31;
    const int warp = tid >> 5;
    const int wm = (warp >> 2) * 64;
    const int wn = (warp & 3) * 32;
    const int bm = blockIdx.y * 128;
    const int bn = blockIdx.x * 128;
    const int NK  = K >> 5;                 // 32-half chunks
    const int KPh = K >> 1;                 // kpairs per weight row

    float acc[4][4][4];
#pragma unroll
    for (int a = 0; a < 4; a++)
#pragma unroll
        for (int b = 0; b < 4; b++)
#pragma unroll
            for (int c = 0; c < 4; c++) acc[a][b][c] = 0.f;

    auto loadc = [&](int kc, int st) {
#pragma unroll
        for (int i = 0; i < 2; i++) {
            const int idx = tid + 256 * i;
            const int row = idx >> 2, seg = idx & 3;
            int gr = bm + row; gr = gr < M ? gr : M - 1;
            cp16(sbA + st * T_STB + row * 80 + seg * 16,
                 (const char*)A16 + ((size_t)gr * K + kc * 32 + seg * 8) * 2);
        }
#pragma unroll
        for (int i = 0; i < 2; i++) {
            const int idx = tid + 256 * i;
            const int row = idx >> 2, seg = idx & 3;
            const bool ok = (bn + row) < N;
            const int gn = ok ? (bn + row) : (N - 1);
            cp16z(sbB + st * T_STB + row * 80 + seg * 16,
                  WpT + (size_t)gn * KPh + kc * KPC + seg * 4, ok ? 16u : 0u);
        }
        cpcommit();
    };

#pragma unroll
    for (int p = 0; p < NSTG - 1; p++) loadc(p, p);

    // per-thread ldmatrix row address components
    const uint32_t lrow = (lane & 15) * 80 + ((lane >> 4) << 4);   // row-in-16 + (kp+4) select
    const int r = lane >> 2;

    for (int kc = 0; kc < NK; kc++) {
        const int st = kc & (NSTG - 1);
        {
            const int rem = NK - 1 - kc;
            if (rem >= 2) cpwait<2>(); else if (rem == 1) cpwait<1>(); else cpwait<0>();
        }
        __syncthreads();
        const int nxt = kc + NSTG - 1;
        if (nxt < NK) loadc(nxt, nxt & (NSTG - 1));

        const uint32_t aB = sbA + st * T_STB + lrow;
        const uint32_t bB = sbB + st * T_STB + lrow;
#pragma unroll
        for (int ks = 0; ks < KPC; ks += 8) {
            uint32_t af[4][4], bf[4][2];
#pragma unroll
            for (int mt = 0; mt < 4; mt++)
                LDSM4(af[mt][0], af[mt][1], af[mt][2], af[mt][3],
                      aB + (wm + mt * 16) * 80 + ks * 4);
#pragma unroll
            for (int nt2 = 0; nt2 < 2; nt2++)
                LDSM4(bf[2 * nt2][0], bf[2 * nt2 + 1][0],
                      bf[2 * nt2][1], bf[2 * nt2 + 1][1],
                      bB + (wn + nt2 * 16) * 80 + ks * 4);
#pragma unroll
            for (int mt = 0; mt < 4; mt++)
#pragma unroll
                for (int nt = 0; nt < 4; nt++)
                    mma_f16(acc[mt][nt], af[mt], bf[nt]);
        }
    }

    float*  Cf = (float*)Craw;
    __half* Ch = (__half*)Craw;
    const int c2 = (lane & 3) * 2;
#pragma unroll
    for (int mt = 0; mt < 4; mt++) {
        const int r0 = bm + wm + mt * 16 + r;
#pragma unroll
        for (int nt = 0; nt < 4; nt++) {
            const int cc = bn + wn + nt * 8 + c2;
            if (cc < N) {
                const float b0 = bias[cc], b1 = bias[cc + 1];
#pragma unroll
                for (int hh = 0; hh < 2; hh++) {
                    const int rr = r0 + hh * 8;
                    if (rr < M) {
                        float ox = acc[mt][nt][hh * 2 + 0] + b0;
                        float oy = acc[mt][nt][hh * 2 + 1] + b1;
                        if (RELU) { ox = fmaxf(ox, 0.f); oy = fmaxf(oy, 0.f); }
                        if (OUT_HALF) {
                            *(uint32_t*)&Ch[(size_t)rr * N + cc] = packh2(ox, oy);
                        } else {
                            *(float2*)&Cf[(size_t)rr * N + cc] = make_float2(ox, oy);
                        }
                    }
                }
            }
        }
    }
}

// ---------------- conversion kernels ----------------
__global__ __launch_bounds__(256)
void conv_src_q(const float2* __restrict__ src, const float2* __restrict__ pos,
                uint32_t* __restrict__ src16, uint32_t* __restrict__ q16, int n) {
    int i = blockIdx.x * 256 + threadIdx.x;
    if (i < n) {
        float2 s = src[i], p = pos[i];
        src16[i] = packh2(s.x, s.y);
        q16[i]   = packh2(s.x + p.x, s.y + p.y);
    }
}
// WpT[n][kp] = half2(W[2kp][n], W[2kp+1][n]); 32x32 smem tile transpose
__global__ __launch_bounds__(256)
void w_to_pairsT(const float* __restrict__ W, uint32_t* __restrict__ WpT,
                 int KP, int N) {
    __shared__ uint32_t t[32][33];
    const int kp0 = blockIdx.y * 32, n0 = blockIdx.x * 32;
    const int x = threadIdx.x & 31, y = threadIdx.x >> 5;   // 32 x 8
#pragma unroll
    for (int yy = y; yy < 32; yy += 8) {
        const int kp = kp0 + yy, n = n0 + x;
        if (kp < KP && n < N)
            t[yy][x] = packh2(W[(size_t)(2 * kp) * N + n], W[(size_t)(2 * kp + 1) * N + n]);
    }
    __syncthreads();
#pragma unroll
    for (int yy = y; yy < 32; yy += 8) {
        const int n = n0 + yy, kp = kp0 + x;
        if (n < N && kp < KP) WpT[(size_t)n * KP + kp] = t[x][yy];
    }
}
__global__ __launch_bounds__(256)
void concat_bias(const float* __restrict__ a, const float* __restrict__ b,
                 float* __restrict__ o) {
    int i = threadIdx.x + blockIdx.x * 256;
    if (i < 320) o[i] = a[i];
    else if (i < 480) o[i] = b[i - 320];
}

// ---------------- deformable sampling (fp16 value, 64 threads/query) ----------------
__global__ __launch_bounds__(64)
void sample_kernel(const uint32_t* __restrict__ val16,  // half2 [B*L][128]
                   const float* __restrict__ ref,
                   const float* __restrict__ oa,        // [B*L][480] off|log
                   uint32_t* __restrict__ acc16)        // half2 [B*L][128]
{
    const int q = blockIdx.x;
    const int b = q / L_Q;
    const int t = threadIdx.x;

    __shared__ float s_off[320];
    __shared__ float s_log[160];
    __shared__ float s_ref[10];

    const float* row = oa + (size_t)q * 480;
#pragma unroll
    for (int i = t; i < 320; i += 64) s_off[i] = row[i];
#pragma unroll
    for (int i = t; i < 160; i += 64) s_log[i] = row[320 + i];
    if (t < 10) s_ref[t] = ref[(size_t)q * 10 + t];
    __syncthreads();

    const int h  = t >> 3;
    const int ci = (t & 7) * 4;

    float m = -1e30f;
#pragma unroll
    for (int p = 0; p < 20; p++) m = fmaxf(m, s_log[h * 20 + p]);
    float e[20], ssum = 0.f;
#pragma unroll
    for (int p = 0; p < 20; p++) { e[p] = __expf(s_log[h * 20 + p] - m); ssum += e[p]; }
    const float inv = 1.0f / ssum;

    float4 a = make_float4(0.f, 0.f, 0.f, 0.f);
    const uint32_t* vbase = val16 + (size_t)b * L_Q * 128 + h * 16 + (ci >> 1);

#pragma unroll
    for (int l = 0; l < 5; l++) {
        const int Hs = c_HW[l], Ws = c_HW[l];
        const uint32_t* vlvl = vbase + (size_t)c_start[l] * 128;
        const float rx = s_ref[l * 2 + 0];
        const float ry = s_ref[l * 2 + 1];
#pragma unroll
        for (int p = 0; p < 4; p++) {
            const float ox = s_off[h * 40 + l * 8 + p * 2 + 0];
            const float oy = s_off[h * 40 + l * 8 + p * 2 + 1];
            const float w  = e[l * 4 + p] * inv;

            const float locx = rx + ox / (float)Ws;
            const float locy = ry + oy / (float)Hs;
            const float px = locx * (float)Ws - 0.5f;
            const float py = locy * (float)Hs - 0.5f;

            const float x0f = floorf(px), y0f = floorf(py);
            const float lx = px - x0f, ly = py - y0f;
            const int x0 = (int)x0f, y0 = (int)y0f;
            const int x1 = x0 + 1,  y1 = y0 + 1;

            const bool vx0 = (x0 >= 0) & (x0 < Ws);
            const bool vx1 = (x1 >= 0) & (x1 < Ws);
            const bool vy0 = (y0 >= 0) & (y0 < Hs);
            const bool vy1 = (y1 >= 0) & (y1 < Hs);

#pragma unroll
            for (int corner = 0; corner < 4; corner++) {
                const int dx = corner & 1, dy = corner >> 1;
                const bool ok = (dx ? vx1 : vx0) & (dy ? vy1 : vy0);
                if (ok) {
                    const float wx = dx ? lx : (1.f - lx);
                    const float wy = dy ? ly : (1.f - ly);
                    const float cw = w * wx * wy;
                    const int yy = y0 + dy, xx = x0 + dx;
                    uint2 u = *(const uint2*)(vlvl + (size_t)(yy * Ws + xx) * 128);
                    float2 v0 = __half22float2(*(__half2*)&u.x);
                    float2 v1 = __half22float2(*(__half2*)&u.y);
                    a.x = fmaf(cw, v0.x, a.x); a.y = fmaf(cw, v0.y, a.y);
                    a.z = fmaf(cw, v1.x, a.z); a.w = fmaf(cw, v1.y, a.w);
                }
            }
        }
    }
    uint2 o;
    o.x = packh2(a.x, a.y);
    o.y = packh2(a.z, a.w);
    *(uint2*)&acc16[(size_t)q * 128 + h * 16 + (ci >> 1)] = o;
}

// ---------------- fused add + layernorm (optional fp16 copy) ----------------
template<bool STORE_HALF>
__global__ __launch_bounds__(256)
void add_ln_kernel(const float* __restrict__ a, const float* __restrict__ b,
                   const float* __restrict__ g, const float* __restrict__ be,
                   float* __restrict__ out, uint32_t* __restrict__ out16, int M)
{
    const int warp = threadIdx.x >> 5;
    const int lane = threadIdx.x & 31;
    const int row  = blockIdx.x * 8 + warp;
    if (row >= M) return;

    const float* ar = a + (size_t)row * 256;
    const float* br = b + (size_t)row * 256;

    float4 v0 = *(const float4*)(ar + lane * 4);
    float4 v1 = *(const float4*)(ar + 128 + lane * 4);
    float4 w0 = *(const float4*)(br + lane * 4);
    float4 w1 = *(const float4*)(br + 128 + lane * 4);

    float v[8];
    v[0] = v0.x + w0.x; v[1] = v0.y + w0.y; v[2] = v0.z + w0.z; v[3] = v0.w + w0.w;
    v[4] = v1.x + w1.x; v[5] = v1.y + w1.y; v[6] = v1.z + w1.z; v[7] = v1.w + w1.w;

    float s = 0.f, sq = 0.f;
#pragma unroll
    for (int i = 0; i < 8; i++) { s += v[i]; sq = fmaf(v[i], v[i], sq); }
#pragma unroll
    for (int o = 16; o; o >>= 1) {
        s  += __shfl_xor_sync(0xffffffffu, s,  o);
        sq += __shfl_xor_sync(0xffffffffu, sq, o);
    }
    const float mean = s * (1.f / 256.f);
    const float var  = sq * (1.f / 256.f) - mean * mean;
    const float inv  = rsqrtf(var + 1e-5f);

    float* orow = out + (size_t)row * 256;
#pragma unroll
    for (int half = 0; half < 2; half++) {
        const int c = half * 128 + lane * 4;
        float4 o;
        float* vv = v + half * 4;
        o.x = (vv[0] - mean) * inv * g[c + 0] + be[c + 0];
        o.y = (vv[1] - mean) * inv * g[c + 1] + be[c + 1];
        o.z = (vv[2] - mean) * inv * g[c + 2] + be[c + 2];
        o.w = (vv[3] - mean) * inv * g[c + 3] + be[c + 3];
        *(float4*)&orow[c] = o;
        if (STORE_HALF) {
            uint2 u;
            u.x = packh2(o.x, o.y);
            u.y = packh2(o.z, o.w);
            *(uint2*)&out16[(size_t)row * 128 + (c >> 1)] = u;
        }
    }
}

// ---------------- launch ----------------
extern "C" void kernel_launch(void* const* d_in, const int* in_sizes, int n_in,
                              void* d_out, int out_size)
{
    const float* src  = (const float*)d_in[0];
    const float* pos  = (const float*)d_in[1];
    const float* ref  = (const float*)d_in[2];
    const float* wv   = (const float*)d_in[3];
    const float* bv   = (const float*)d_in[4];
    const float* wo   = (const float*)d_in[5];
    const float* bo   = (const float*)d_in[6];
    const float* wa   = (const float*)d_in[7];
    const float* ba   = (const float*)d_in[8];
    const float* wout = (const float*)d_in[9];
    const float* bout = (const float*)d_in[10];
    const float* ln1g = (const float*)d_in[11];
    const float* ln1b = (const float*)d_in[12];
    const float* w1   = (const float*)d_in[13];
    const float* b1   = (const float*)d_in[14];
    const float* w2   = (const float*)d_in[15];
    const float* b2   = (const float*)d_in[16];
    const float* ln2g = (const float*)d_in[17];
    const float* ln2b = (const float*)d_in[18];
    float* out = (float*)d_out;

    const int M  = in_sizes[0] / CDIM;       // 26686
    const int mt = (M + 127) / 128;          // 209

    float *oap, *src2, *xp, *yp, *boap;
    uint32_t *src16, *q16, *val16, *acc16, *x16, *h16;
    uint32_t *wvp, *woap, *woutp, *w1p, *w2p;
    cudaGetSymbolAddress((void**)&oap,   g_oa);
    cudaGetSymbolAddress((void**)&src2,  g_src2);
    cudaGetSymbolAddress((void**)&xp,    g_x);
    cudaGetSymbolAddress((void**)&yp,    g_y);
    cudaGetSymbolAddress((void**)&src16, g_src16);
    cudaGetSymbolAddress((void**)&q16,   g_q16);
    cudaGetSymbolAddress((void**)&val16, g_val16);
    cudaGetSymbolAddress((void**)&acc16, g_acc16);
    cudaGetSymbolAddress((void**)&x16,   g_x16);
    cudaGetSymbolAddress((void**)&h16,   g_h16);
    cudaGetSymbolAddress((void**)&wvp,   g_wvp);
    cudaGetSymbolAddress((void**)&woap,  g_woap);
    cudaGetSymbolAddress((void**)&woutp, g_woutp);
    cudaGetSymbolAddress((void**)&w1p,   g_w1p);
    cudaGetSymbolAddress((void**)&w2p,   g_w2p);
    cudaGetSymbolAddress((void**)&boap,  g_boa);

    cudaFuncSetAttribute(gemm_h<false, false>, cudaFuncAttributeMaxDynamicSharedMemorySize, SMEM_GEMM);
    cudaFuncSetAttribute(gemm_h<false, true>,  cudaFuncAttributeMaxDynamicSharedMemorySize, SMEM_GEMM);
    cudaFuncSetAttribute(gemm_h<true,  true>,  cudaFuncAttributeMaxDynamicSharedMemorySize, SMEM_GEMM);

    // conversions
    const int n2 = M * 128;
    conv_src_q<<<(n2 + 255) / 256, 256>>>((const float2*)src, (const float2*)pos, src16, q16, n2);
    w_to_pairsT<<<dim3(8,  4),  256>>>(wv,   wvp,               128,  256);
    w_to_pairsT<<<dim3(10, 4),  256>>>(wo,   woap,              128,  320);
    w_to_pairsT<<<dim3(5,  4),  256>>>(wa,   woap + 320 * 128,  128,  160);
    w_to_pairsT<<<dim3(8,  4),  256>>>(wout, woutp,             128,  256);
    w_to_pairsT<<<dim3(64, 4),  256>>>(w1,   w1p,               128,  2048);
    w_to_pairsT<<<dim3(8,  32), 256>>>(w2,   w2p,               1024, 256);
    concat_bias<<<2, 256>>>(bo, ba, boap);

    // 1) value = src @ wv + bv -> fp16
    gemm_h<false, true><<<dim3(2, mt), 256, SMEM_GEMM>>>((const __half*)src16, wvp, bv, val16, M, 256, 256);
    // 2+3) [offsets|logits] = q @ [wo|wa] + [bo|ba]
    gemm_h<false, false><<<dim3(4, mt), 256, SMEM_GEMM>>>((const __half*)q16, woap, boap, oap, M, 480, 256);
    // 4) deformable sampling -> acc16
    sample_kernel<<<M, 64>>>(val16, ref, oap, acc16);
    // 5) src2 = acc @ wout + bout
    gemm_h<false, false><<<dim3(2, mt), 256, SMEM_GEMM>>>((const __half*)acc16, woutp, bout, src2, M, 256, 256);
    // 6) x = LN(src + src2)  (+ fp16 copy)
    add_ln_kernel<true><<<(M + 7) / 8, 256>>>(src, src2, ln1g, ln1b, xp, x16, M);
    // 7) h = relu(x @ w1 + b1) -> fp16
    gemm_h<true, true><<<dim3(16, mt), 256, SMEM_GEMM>>>((const __half*)x16, w1p, b1, h16, M, 2048, 256);
    // 8) y = h @ w2 + b2
    gemm_h<false, false><<<dim3(2, mt), 256, SMEM_GEMM>>>((const __half*)h16, w2p, b2, yp, M, 256, 2048);
    // 9) out = LN(x + y)
    add_ln_kernel<false><<<(M + 7) / 8, 256>>>(xp, yp, ln2g, ln2b, out, nullptr, M);
}

// round 16
// speedup vs baseline: 1.1076x; 1.1076x over previous
#include <cuda_runtime.h>
#include <cuda_fp16.h>
#include <cstdint>

// ---------------- problem constants ----------------
#define L_Q   13343
#define BLMAX 26686
#define CDIM  256

__constant__ int c_HW[5]    = {100, 50, 25, 13, 7};
__constant__ int c_start[5] = {0, 10000, 12500, 13125, 13294};

// ---------------- scratch (static device globals; no allocs) ----------------
__device__ float    g_oa   [(size_t)BLMAX * 480];   // offsets(320) | logits(160)
__device__ float    g_value[(size_t)BLMAX * 256];
__device__ float    g_src2 [(size_t)BLMAX * 256];
__device__ float    g_x    [(size_t)BLMAX * 256];
__device__ float    g_y    [(size_t)BLMAX * 256];
// fp16 activations (half2 words)
__device__ uint32_t g_src16 [(size_t)BLMAX * 128];
__device__ uint32_t g_q16   [(size_t)BLMAX * 128];
__device__ uint32_t g_acc16 [(size_t)BLMAX * 128];
__device__ uint32_t g_x16   [(size_t)BLMAX * 128];
__device__ uint32_t g_h16   [(size_t)BLMAX * 1024];
// fp16 weights, k-pair interleaved: Wp[kp][n] = half2(W[2kp][n], W[2kp+1][n])
__device__ uint32_t g_wvp   [128 * 256];
__device__ uint32_t g_woap  [128 * 480];            // wo(320) | wa(160) columns
__device__ uint32_t g_woutp [128 * 256];
__device__ uint32_t g_w1p   [128 * 2048];
__device__ uint32_t g_w2p   [1024 * 256];
__device__ float    g_boa   [480];                  // bo | ba

// ---------------- ptx helpers ----------------
__device__ __forceinline__ uint32_t s2u(const void* p) {
    uint32_t a;
    asm("{ .reg .u64 t; cvta.to.shared.u64 t, %1; cvt.u32.u64 %0, t; }" : "=r"(a) : "l"(p));
    return a;
}
__device__ __forceinline__ void cp16(uint32_t s, const void* g) {
    asm volatile("cp.async.cg.shared.global [%0], [%1], 16;\n" :: "r"(s), "l"(g));
}
__device__ __forceinline__ void cp16z(uint32_t s, const void* g, uint32_t bytes) {
    asm volatile("cp.async.cg.shared.global [%0], [%1], 16, %2;\n"
                 :: "r"(s), "l"(g), "r"(bytes));
}
__device__ __forceinline__ void cpcommit() { asm volatile("cp.async.commit_group;\n" ::: "memory"); }
template<int N> __device__ __forceinline__ void cpwait() {
    asm volatile("cp.async.wait_group %0;\n" :: "n"(N) : "memory");
}
__device__ __forceinline__ void mma_f16(float* d, const uint32_t* a, const uint32_t* b) {
    asm volatile(
        "mma.sync.aligned.m16n8k16.row.col.f32.f16.f16.f32 "
        "{%0,%1,%2,%3}, {%4,%5,%6,%7}, {%8,%9}, {%0,%1,%2,%3};\n"
        : "+f"(d[0]), "+f"(d[1]), "+f"(d[2]), "+f"(d[3])
        : "r"(a[0]), "r"(a[1]), "r"(a[2]), "r"(a[3]), "r"(b[0]), "r"(b[1]));
}
__device__ __forceinline__ uint32_t packh2(float lo, float hi) {
    __half2 h = __floats2half2_rn(lo, hi);
    return *(uint32_t*)&h;
}

// ---------------- cp.async pipelined FP16 GEMM (round-11 proven form) ----------------
#define KPC 16
#define ASTRH 20
#define BSTRH 136
#define A_STB (128 * ASTRH * 4)
#define B_STB (KPC * BSTRH * 4)
#define NSTG  4
#define SMEM_GEMM (NSTG * (A_STB + B_STB))

template<bool RELU, bool OUT_HALF>
__global__ __launch_bounds__(256, 2)
void gemm_h(const __half* __restrict__ A16, const uint32_t* __restrict__ Wp,
            const float* __restrict__ bias, void* __restrict__ Craw,
            int M, int N, int K)
{
    extern __shared__ uint32_t smem[];
    const uint32_t sbA = s2u(smem);
    const uint32_t sbB = sbA + NSTG * A_STB;
    uint32_t* uA = smem;
    uint32_t* uB = smem + NSTG * (A_STB / 4);

    const int tid  = threadIdx.x;
    const int lane = tid & 31;
    const int warp = tid >> 5;
    const int wm = (warp >> 2) * 64;
    const int wn = (warp & 3) * 32;
    const int bm = blockIdx.y * 128;
    const int bn = blockIdx.x * 128;
    const int NK = K >> 5;

    float acc[4][4][4];
#pragma unroll
    for (int a = 0; a < 4; a++)
#pragma unroll
        for (int b = 0; b < 4; b++)
#pragma unroll
            for (int c = 0; c < 4; c++) acc[a][b][c] = 0.f;

    auto loadc = [&](int kc, int st) {
#pragma unroll
        for (int i = 0; i < 2; i++) {
            const int idx = tid + 256 * i;
            const int row = idx >> 2, seg = idx & 3;
            int gr = bm + row; gr = gr < M ? gr : M - 1;
            cp16(sbA + st * A_STB + row * (ASTRH * 4) + seg * 16,
                 (const char*)A16 + ((size_t)gr * K + kc * 32 + seg * 8) * 2);
        }
#pragma unroll
        for (int i = 0; i < 2; i++) {
            const int idx = tid + 256 * i;
            const int kr = idx >> 5, seg = idx & 31;
            const int col = bn + seg * 4;
            const int rem = N - col;
            const uint32_t bytes = rem >= 4 ? 16u : (rem > 0 ? (uint32_t)rem * 4u : 0u);
            cp16z(sbB + st * B_STB + kr * (BSTRH * 4) + seg * 16,
                  Wp + (size_t)(kc * KPC + kr) * N + col, bytes);
        }
        cpcommit();
    };

#pragma unroll
    for (int p = 0; p < NSTG - 1; p++) loadc(p, p);

    const int r = lane >> 2, c = lane & 3;

    for (int kc = 0; kc < NK; kc++) {
        const int st = kc & (NSTG - 1);
        {
            const int rem = NK - 1 - kc;
            if (rem >= 2) cpwait<2>(); else if (rem == 1) cpwait<1>(); else cpwait<0>();
        }
        __syncthreads();
        const int nxt = kc + NSTG - 1;
        if (nxt < NK) loadc(nxt, nxt & (NSTG - 1));

        const uint32_t* As = uA + st * (A_STB / 4);
        const uint32_t* Bs = uB + st * (B_STB / 4);
#pragma unroll
        for (int ks = 0; ks < KPC; ks += 8) {
            uint32_t af[4][4], bf[4][2];
#pragma unroll
            for (int mt = 0; mt < 4; mt++) {
                const int rr = wm + mt * 16 + r;
                af[mt][0] = As[(rr) * ASTRH + ks + c];
                af[mt][1] = As[(rr + 8) * ASTRH + ks + c];
                af[mt][2] = As[(rr) * ASTRH + ks + c + 4];
                af[mt][3] = As[(rr + 8) * ASTRH + ks + c + 4];
            }
#pragma unroll
            for (int nt = 0; nt < 4; nt++) {
                const int cc = wn + nt * 8 + r;
                bf[nt][0] = Bs[(ks + c) * BSTRH + cc];
                bf[nt][1] = Bs[(ks + c + 4) * BSTRH + cc];
            }
#pragma unroll
            for (int mt = 0; mt < 4; mt++)
#pragma unroll
                for (int nt = 0; nt < 4; nt++)
                    mma_f16(acc[mt][nt], af[mt], bf[nt]);
        }
    }

    float*  Cf = (float*)Craw;
    __half* Ch = (__half*)Craw;
    const int c2 = (lane & 3) * 2;
#pragma unroll
    for (int mt = 0; mt < 4; mt++) {
        const int r0 = bm + wm + mt * 16 + r;
#pragma unroll
        for (int nt = 0; nt < 4; nt++) {
            const int cc = bn + wn + nt * 8 + c2;
            if (cc < N) {
                const float b0 = bias[cc], b1 = bias[cc + 1];
#pragma unroll
                for (int hh = 0; hh < 2; hh++) {
                    const int rr = r0 + hh * 8;
                    if (rr < M) {
                        float ox = acc[mt][nt][hh * 2 + 0] + b0;
                        float oy = acc[mt][nt][hh * 2 + 1] + b1;
                        if (RELU) { ox = fmaxf(ox, 0.f); oy = fmaxf(oy, 0.f); }
                        if (OUT_HALF) {
                            *(uint32_t*)&Ch[(size_t)rr * N + cc] = packh2(ox, oy);
                        } else {
                            *(float2*)&Cf[(size_t)rr * N + cc] = make_float2(ox, oy);
                        }
                    }
                }
            }
        }
    }
}

// ---------------- conversion kernels ----------------
__global__ __launch_bounds__(256)
void conv_src_q(const float2* __restrict__ src, const float2* __restrict__ pos,
                uint32_t* __restrict__ src16, uint32_t* __restrict__ q16, int n) {
    int i = blockIdx.x * 256 + threadIdx.x;
    if (i < n) {
        float2 s = src[i], p = pos[i];
        src16[i] = packh2(s.x, s.y);
        q16[i]   = packh2(s.x + p.x, s.y + p.y);
    }
}
__global__ __launch_bounds__(256)
void w_to_pairs(const float* __restrict__ W, uint32_t* __restrict__ Wp,
                int KP, int N, int NP) {
    int i = blockIdx.x * 256 + threadIdx.x;
    if (i < KP * N) {
        int kp = i / N, n = i - kp * N;
        Wp[(size_t)kp * NP + n] = packh2(W[(size_t)(2 * kp) * N + n], W[(size_t)(2 * kp + 1) * N + n]);
    }
}
__global__ __launch_bounds__(256)
void concat_bias(const float* __restrict__ a, const float* __restrict__ b,
                 float* __restrict__ o) {
    int i = threadIdx.x + blockIdx.x * 256;
    if (i < 320) o[i] = a[i];
    else if (i < 480) o[i] = b[i - 320];
}

// ---------------- deformable sampling: two-phase (precompute + gather) ----------------
// 64 threads per query. Phase 1a: 8 threads -> per-head softmax stats.
// Phase 1b: 64 threads -> 160 (head,point) precomputed corner weights + offsets.
// Phase 2: pure gather: per point 2 LDS.128 + 4 LDG.128 + 16 FMA.
__global__ __launch_bounds__(64)
void sample_kernel(const float* __restrict__ value,   // [B*L][256] fp32
                   const float* __restrict__ ref,
                   const float* __restrict__ oa,      // [B*L][480] off|log
                   uint32_t* __restrict__ acc16)      // half2 [B*L][128]
{
    const int q = blockIdx.x;
    const int b = q / L_Q;
    const int t = threadIdx.x;

    __shared__ float  s_off[320];
    __shared__ float  s_log[160];
    __shared__ float  s_ref[10];
    __shared__ float  s_m[8], s_inv[8];
    __shared__ float4 s_cw[160];
    __shared__ int4   s_id[160];

    const float* row = oa + (size_t)q * 480;
#pragma unroll
    for (int i = t; i < 320; i += 64) s_off[i] = row[i];
#pragma unroll
    for (int i = t; i < 160; i += 64) s_log[i] = row[320 + i];
    if (t < 10) s_ref[t] = ref[(size_t)q * 10 + t];
    __syncthreads();

    // phase 1a: per-head softmax stats
    if (t < 8) {
        float m = -1e30f;
#pragma unroll
        for (int p = 0; p < 20; p++) m = fmaxf(m, s_log[t * 20 + p]);
        float ss = 0.f;
#pragma unroll
        for (int p = 0; p < 20; p++) ss += __expf(s_log[t * 20 + p] - m);
        s_m[t] = m; s_inv[t] = 1.0f / ss;
    }
    __syncthreads();

    // phase 1b: precompute combined corner weights + word offsets (160 pairs)
#pragma unroll
    for (int i = t; i < 160; i += 64) {
        const int h  = i / 20;
        const int lp = i - h * 20;
        const int l  = lp >> 2;
        const int Ws = c_HW[l];              // H == W
        const int base = c_start[l];

        const float w = __expf(s_log[i] - s_m[h]) * s_inv[h];
        const float ox = s_off[h * 40 + lp * 2 + 0];
        const float oy = s_off[h * 40 + lp * 2 + 1];
        const float rx = s_ref[l * 2 + 0];
        const float ry = s_ref[l * 2 + 1];

        const float locx = rx + ox / (float)Ws;
        const float locy = ry + oy / (float)Ws;
        const float px = locx * (float)Ws - 0.5f;
        const float py = locy * (float)Ws - 0.5f;

        const float x0f = floorf(px), y0f = floorf(py);
        const float lx = px - x0f, ly = py - y0f;
        const int x0 = (int)x0f, y0 = (int)y0f;
        const int x1 = x0 + 1,  y1 = y0 + 1;

        const bool vx0 = (x0 >= 0) & (x0 < Ws);
        const bool vx1 = (x1 >= 0) & (x1 < Ws);
        const bool vy0 = (y0 >= 0) & (y0 < Ws);
        const bool vy1 = (y1 >= 0) & (y1 < Ws);

        const float wx0 = 1.f - lx, wx1 = lx;
        const float wy0 = 1.f - ly, wy1 = ly;

        float4 cw; int4 id;
        const bool c00 = vx0 & vy0, c10 = vx1 & vy0, c01 = vx0 & vy1, c11 = vx1 & vy1;
        cw.x = c00 ? w * wx0 * wy0 : 0.f;  id.x = c00 ? (base + y0 * Ws + x0) * 256 : 0;
        cw.y = c10 ? w * wx1 * wy0 : 0.f;  id.y = c10 ? (base + y0 * Ws + x1) * 256 : 0;
        cw.z = c01 ? w * wx0 * wy1 : 0.f;  id.z = c01 ? (base + y1 * Ws + x0) * 256 : 0;
        cw.w = c11 ? w * wx1 * wy1 : 0.f;  id.w = c11 ? (base + y1 * Ws + x1) * 256 : 0;
        s_cw[i] = cw; s_id[i] = id;
    }
    __syncthreads();

    // phase 2: gather
    const int h  = t >> 3;
    const int ci = (t & 7) * 4;
    const float* vb = value + (size_t)b * L_Q * 256 + h * 32 + ci;

    float4 a0 = make_float4(0.f, 0.f, 0.f, 0.f);
    float4 a1 = a0, a2 = a0, a3 = a0;

#pragma unroll 5
    for (int p = 0; p < 20; p++) {
        const float4 cw = s_cw[h * 20 + p];
        const int4   id = s_id[h * 20 + p];
        float4 v;
        v = *(const float4*)(vb + id.x);
        a0.x = fmaf(cw.x, v.x, a0.x); a0.y = fmaf(cw.x, v.y, a0.y);
        a0.z = fmaf(cw.x, v.z, a0.z); a0.w = fmaf(cw.x, v.w, a0.w);
        v = *(const float4*)(vb + id.y);
        a1.x = fmaf(cw.y, v.x, a1.x); a1.y = fmaf(cw.y, v.y, a1.y);
        a1.z = fmaf(cw.y, v.z, a1.z); a1.w = fmaf(cw.y, v.w, a1.w);
        v = *(const float4*)(vb + id.z);
        a2.x = fmaf(cw.z, v.x, a2.x); a2.y = fmaf(cw.z, v.y, a2.y);
        a2.z = fmaf(cw.z, v.z, a2.z); a2.w = fmaf(cw.z, v.w, a2.w);
        v = *(const float4*)(vb + id.w);
        a3.x = fmaf(cw.w, v.x, a3.x); a3.y = fmaf(cw.w, v.y, a3.y);
        a3.z = fmaf(cw.w, v.z, a3.z); a3.w = fmaf(cw.w, v.w, a3.w);
    }
    float4 a;
    a.x = (a0.x + a1.x) + (a2.x + a3.x);
    a.y = (a0.y + a1.y) + (a2.y + a3.y);
    a.z = (a0.z + a1.z) + (a2.z + a3.z);
    a.w = (a0.w + a1.w) + (a2.w + a3.w);

    uint2 o;
    o.x = packh2(a.x, a.y);
    o.y = packh2(a.z, a.w);
    *(uint2*)&acc16[(size_t)q * 128 + h * 16 + (ci >> 1)] = o;
}

// ---------------- fused add + layernorm (optional fp16 copy) ----------------
template<bool STORE_HALF>
__global__ __launch_bounds__(256)
void add_ln_kernel(const float* __restrict__ a, const float* __restrict__ b,
                   const float* __restrict__ g, const float* __restrict__ be,
                   float* __restrict__ out, uint32_t* __restrict__ out16, int M)
{
    const int warp = threadIdx.x >> 5;
    const int lane = threadIdx.x & 31;
    const int row  = blockIdx.x * 8 + warp;
    if (row >= M) return;

    const float* ar = a + (size_t)row * 256;
    const float* br = b + (size_t)row * 256;

    float4 v0 = *(const float4*)(ar + lane * 4);
    float4 v1 = *(const float4*)(ar + 128 + lane * 4);
    float4 w0 = *(const float4*)(br + lane * 4);
    float4 w1 = *(const float4*)(br + 128 + lane * 4);

    float v[8];
    v[0] = v0.x + w0.x; v[1] = v0.y + w0.y; v[2] = v0.z + w0.z; v[3] = v0.w + w0.w;
    v[4] = v1.x + w1.x; v[5] = v1.y + w1.y; v[6] = v1.z + w1.z; v[7] = v1.w + w1.w;

    float s = 0.f, sq = 0.f;
#pragma unroll
    for (int i = 0; i < 8; i++) { s += v[i]; sq = fmaf(v[i], v[i], sq); }
#pragma unroll
    for (int o = 16; o; o >>= 1) {
        s  += __shfl_xor_sync(0xffffffffu, s,  o);
        sq += __shfl_xor_sync(0xffffffffu, sq, o);
    }
    const float mean = s * (1.f / 256.f);
    const float var  = sq * (1.f / 256.f) - mean * mean;
    const float inv  = rsqrtf(var + 1e-5f);

    float* orow = out + (size_t)row * 256;
#pragma unroll
    for (int half = 0; half < 2; half++) {
        const int c = half * 128 + lane * 4;
        float4 o;
        float* vv = v + half * 4;
        o.x = (vv[0] - mean) * inv * g[c + 0] + be[c + 0];
        o.y = (vv[1] - mean) * inv * g[c + 1] + be[c + 1];
        o.z = (vv[2] - mean) * inv * g[c + 2] + be[c + 2];
        o.w = (vv[3] - mean) * inv * g[c + 3] + be[c + 3];
        *(float4*)&orow[c] = o;
        if (STORE_HALF) {
            uint2 u;
            u.x = packh2(o.x, o.y);
            u.y = packh2(o.z, o.w);
            *(uint2*)&out16[(size_t)row * 128 + (c >> 1)] = u;
        }
    }
}

// ---------------- launch ----------------
extern "C" void kernel_launch(void* const* d_in, const int* in_sizes, int n_in,
                              void* d_out, int out_size)
{
    const float* src  = (const float*)d_in[0];
    const float* pos  = (const float*)d_in[1];
    const float* ref  = (const float*)d_in[2];
    const float* wv   = (const float*)d_in[3];
    const float* bv   = (const float*)d_in[4];
    const float* wo   = (const float*)d_in[5];
    const float* bo   = (const float*)d_in[6];
    const float* wa   = (const float*)d_in[7];
    const float* ba   = (const float*)d_in[8];
    const float* wout = (const float*)d_in[9];
    const float* bout = (const float*)d_in[10];
    const float* ln1g = (const float*)d_in[11];
    const float* ln1b = (const float*)d_in[12];
    const float* w1   = (const float*)d_in[13];
    const float* b1   = (const float*)d_in[14];
    const float* w2   = (const float*)d_in[15];
    const float* b2   = (const float*)d_in[16];
    const float* ln2g = (const float*)d_in[17];
    const float* ln2b = (const float*)d_in[18];
    float* out = (float*)d_out;

    const int M  = in_sizes[0] / CDIM;       // 26686
    const int mt = (M + 127) / 128;          // 209

    float *oap, *valp, *src2, *xp, *yp, *boap;
    uint32_t *src16, *q16, *acc16, *x16, *h16;
    uint32_t *wvp, *woap, *woutp, *w1p, *w2p;
    cudaGetSymbolAddress((void**)&oap,   g_oa);
    cudaGetSymbolAddress((void**)&valp,  g_value);
    cudaGetSymbolAddress((void**)&src2,  g_src2);
    cudaGetSymbolAddress((void**)&xp,    g_x);
    cudaGetSymbolAddress((void**)&yp,    g_y);
    cudaGetSymbolAddress((void**)&src16, g_src16);
    cudaGetSymbolAddress((void**)&q16,   g_q16);
    cudaGetSymbolAddress((void**)&acc16, g_acc16);
    cudaGetSymbolAddress((void**)&x16,   g_x16);
    cudaGetSymbolAddress((void**)&h16,   g_h16);
    cudaGetSymbolAddress((void**)&wvp,   g_wvp);
    cudaGetSymbolAddress((void**)&woap,  g_woap);
    cudaGetSymbolAddress((void**)&woutp, g_woutp);
    cudaGetSymbolAddress((void**)&w1p,   g_w1p);
    cudaGetSymbolAddress((void**)&w2p,   g_w2p);
    cudaGetSymbolAddress((void**)&boap,  g_boa);

    cudaFuncSetAttribute(gemm_h<false, false>, cudaFuncAttributeMaxDynamicSharedMemorySize, SMEM_GEMM);
    cudaFuncSetAttribute(gemm_h<true,  true>,  cudaFuncAttributeMaxDynamicSharedMemorySize, SMEM_GEMM);

    // conversions
    const int n2 = M * 128;
    conv_src_q<<<(n2 + 255) / 256, 256>>>((const float2*)src, (const float2*)pos, src16, q16, n2);
    w_to_pairs<<<(128 * 256  + 255) / 256, 256>>>(wv,   wvp,        128,  256,  256);
    w_to_pairs<<<(128 * 320  + 255) / 256, 256>>>(wo,   woap,       128,  320,  480);
    w_to_pairs<<<(128 * 160  + 255) / 256, 256>>>(wa,   woap + 320, 128,  160,  480);
    w_to_pairs<<<(128 * 256  + 255) / 256, 256>>>(wout, woutp,      128,  256,  256);
    w_to_pairs<<<(128 * 2048 + 255) / 256, 256>>>(w1,   w1p,        128,  2048, 2048);
    w_to_pairs<<<(1024 * 256 + 255) / 256, 256>>>(w2,   w2p,        1024, 256,  256);
    concat_bias<<<2, 256>>>(bo, ba, boap);

    // 1) value = src @ wv + bv (fp32 out)
    gemm_h<false, false><<<dim3(2, mt), 256, SMEM_GEMM>>>((const __half*)src16, wvp, bv, valp, M, 256, 256);
    // 2+3) [offsets|logits] = q @ [wo|wa] + [bo|ba]
    gemm_h<false, false><<<dim3(4, mt), 256, SMEM_GEMM>>>((const __half*)q16, woap, boap, oap, M, 480, 256);
    // 4) deformable sampling -> acc16
    sample_kernel<<<M, 64>>>(valp, ref, oap, acc16);
    // 5) src2 = acc @ wout + bout
    gemm_h<false, false><<<dim3(2, mt), 256, SMEM_GEMM>>>((const __half*)acc16, woutp, bout, src2, M, 256, 256);
    // 6) x = LN(src + src2)  (+ fp16 copy)
    add_ln_kernel<true><<<(M + 7) / 8, 256>>>(src, src2, ln1g, ln1b, xp, x16, M);
    // 7) h = relu(x @ w1 + b1) -> fp16
    gemm_h<true, true><<<dim3(16, mt), 256, SMEM_GEMM>>>((const __half*)x16, w1p, b1, h16, M, 2048, 256);
    // 8) y = h @ w2 + b2
    gemm_h<false, false><<<dim3(2, mt), 256, SMEM_GEMM>>>((const __half*)h16, w2p, b2, yp, M, 256, 2048);
    // 9) out = LN(x + y)
    add_ln_kernel<false><<<(M + 7) / 8, 256>>>(xp, yp, ln2g, ln2b, out, nullptr, M);
}

// round 17
// speedup vs baseline: 1.2284x; 1.1091x over previous
#include <cuda_runtime.h>
#include <cuda_fp16.h>
#include <cstdint>

// ---------------- problem constants ----------------
#define L_Q   13343
#define BLMAX 26686
#define CDIM  256

__constant__ int c_HW[5]    = {100, 50, 25, 13, 7};
__constant__ int c_start[5] = {0, 10000, 12500, 13125, 13294};

// ---------------- scratch (static device globals; no allocs) ----------------
__device__ float    g_oa   [(size_t)BLMAX * 480];   // offsets(320) | logits(160)
__device__ float    g_src2 [(size_t)BLMAX * 256];
__device__ float    g_x    [(size_t)BLMAX * 256];
__device__ float    g_y    [(size_t)BLMAX * 256];
// fp16 activations (half2 words)
__device__ uint32_t g_src16 [(size_t)BLMAX * 128];
__device__ uint32_t g_q16   [(size_t)BLMAX * 128];
__device__ uint32_t g_val16 [(size_t)BLMAX * 128];
__device__ uint32_t g_acc16 [(size_t)BLMAX * 128];
__device__ uint32_t g_x16   [(size_t)BLMAX * 128];
__device__ uint32_t g_h16   [(size_t)BLMAX * 1024];
// fp16 weights, k-pair interleaved: Wp[kp][n] = half2(W[2kp][n], W[2kp+1][n])
__device__ uint32_t g_wvp   [128 * 256];
__device__ uint32_t g_woap  [128 * 480];            // wo(320) | wa(160) columns
__device__ uint32_t g_woutp [128 * 256];
__device__ uint32_t g_w1p   [128 * 2048];
__device__ uint32_t g_w2p   [1024 * 256];
__device__ float    g_boa   [480];                  // bo | ba

// ---------------- ptx helpers ----------------
__device__ __forceinline__ uint32_t s2u(const void* p) {
    uint32_t a;
    asm("{ .reg .u64 t; cvta.to.shared.u64 t, %1; cvt.u32.u64 %0, t; }" : "=r"(a) : "l"(p));
    return a;
}
__device__ __forceinline__ void cp16(uint32_t s, const void* g) {
    asm volatile("cp.async.cg.shared.global [%0], [%1], 16;\n" :: "r"(s), "l"(g));
}
__device__ __forceinline__ void cp16z(uint32_t s, const void* g, uint32_t bytes) {
    asm volatile("cp.async.cg.shared.global [%0], [%1], 16, %2;\n"
                 :: "r"(s), "l"(g), "r"(bytes));
}
__device__ __forceinline__ void cpcommit() { asm volatile("cp.async.commit_group;\n" ::: "memory"); }
template<int N> __device__ __forceinline__ void cpwait() {
    asm volatile("cp.async.wait_group %0;\n" :: "n"(N) : "memory");
}
__device__ __forceinline__ void mma_f16(float* d, const uint32_t* a, const uint32_t* b) {
    asm volatile(
        "mma.sync.aligned.m16n8k16.row.col.f32.f16.f16.f32 "
        "{%0,%1,%2,%3}, {%4,%5,%6,%7}, {%8,%9}, {%0,%1,%2,%3};\n"
        : "+f"(d[0]), "+f"(d[1]), "+f"(d[2]), "+f"(d[3])
        : "r"(a[0]), "r"(a[1]), "r"(a[2]), "r"(a[3]), "r"(b[0]), "r"(b[1]));
}
__device__ __forceinline__ uint32_t packh2(float lo, float hi) {
    __half2 h = __floats2half2_rn(lo, hi);
    return *(uint32_t*)&h;
}

// ---------------- cp.async pipelined FP16 GEMM (round-11 proven form) ----------------
#define KPC 16
#define ASTRH 20
#define BSTRH 136
#define A_STB (128 * ASTRH * 4)
#define B_STB (KPC * BSTRH * 4)
#define NSTG  4
#define SMEM_GEMM (NSTG * (A_STB + B_STB))

template<bool RELU, bool OUT_HALF>
__global__ __launch_bounds__(256, 2)
void gemm_h(const __half* __restrict__ A16, const uint32_t* __restrict__ Wp,
            const float* __restrict__ bias, void* __restrict__ Craw,
            int M, int N, int K)
{
    extern __shared__ uint32_t smem[];
    const uint32_t sbA = s2u(smem);
    const uint32_t sbB = sbA + NSTG * A_STB;
    uint32_t* uA = smem;
    uint32_t* uB = smem + NSTG * (A_STB / 4);

    const int tid  = threadIdx.x;
    const int lane = tid & 31;
    const int warp = tid >> 5;
    const int wm = (warp >> 2) * 64;
    const int wn = (warp & 3) * 32;
    const int bm = blockIdx.y * 128;
    const int bn = blockIdx.x * 128;
    const int NK = K >> 5;

    float acc[4][4][4];
#pragma unroll
    for (int a = 0; a < 4; a++)
#pragma unroll
        for (int b = 0; b < 4; b++)
#pragma unroll
            for (int c = 0; c < 4; c++) acc[a][b][c] = 0.f;

    auto loadc = [&](int kc, int st) {
#pragma unroll
        for (int i = 0; i < 2; i++) {
            const int idx = tid + 256 * i;
            const int row = idx >> 2, seg = idx & 3;
            int gr = bm + row; gr = gr < M ? gr : M - 1;
            cp16(sbA + st * A_STB + row * (ASTRH * 4) + seg * 16,
                 (const char*)A16 + ((size_t)gr * K + kc * 32 + seg * 8) * 2);
        }
#pragma unroll
        for (int i = 0; i < 2; i++) {
            const int idx = tid + 256 * i;
            const int kr = idx >> 5, seg = idx & 31;
            const int col = bn + seg * 4;
            const int rem = N - col;
            const uint32_t bytes = rem >= 4 ? 16u : (rem > 0 ? (uint32_t)rem * 4u : 0u);
            cp16z(sbB + st * B_STB + kr * (BSTRH * 4) + seg * 16,
                  Wp + (size_t)(kc * KPC + kr) * N + col, bytes);
        }
        cpcommit();
    };

#pragma unroll
    for (int p = 0; p < NSTG - 1; p++) loadc(p, p);

    const int r = lane >> 2, c = lane & 3;

    for (int kc = 0; kc < NK; kc++) {
        const int st = kc & (NSTG - 1);
        {
            const int rem = NK - 1 - kc;
            if (rem >= 2) cpwait<2>(); else if (rem == 1) cpwait<1>(); else cpwait<0>();
        }
        __syncthreads();
        const int nxt = kc + NSTG - 1;
        if (nxt < NK) loadc(nxt, nxt & (NSTG - 1));

        const uint32_t* As = uA + st * (A_STB / 4);
        const uint32_t* Bs = uB + st * (B_STB / 4);
#pragma unroll
        for (int ks = 0; ks < KPC; ks += 8) {
            uint32_t af[4][4], bf[4][2];
#pragma unroll
            for (int mt = 0; mt < 4; mt++) {
                const int rr = wm + mt * 16 + r;
                af[mt][0] = As[(rr) * ASTRH + ks + c];
                af[mt][1] = As[(rr + 8) * ASTRH + ks + c];
                af[mt][2] = As[(rr) * ASTRH + ks + c + 4];
                af[mt][3] = As[(rr + 8) * ASTRH + ks + c + 4];
            }
#pragma unroll
            for (int nt = 0; nt < 4; nt++) {
                const int cc = wn + nt * 8 + r;
                bf[nt][0] = Bs[(ks + c) * BSTRH + cc];
                bf[nt][1] = Bs[(ks + c + 4) * BSTRH + cc];
            }
#pragma unroll
            for (int mt = 0; mt < 4; mt++)
#pragma unroll
                for (int nt = 0; nt < 4; nt++)
                    mma_f16(acc[mt][nt], af[mt], bf[nt]);
        }
    }

    float*  Cf = (float*)Craw;
    __half* Ch = (__half*)Craw;
    const int c2 = (lane & 3) * 2;
#pragma unroll
    for (int mt = 0; mt < 4; mt++) {
        const int r0 = bm + wm + mt * 16 + r;
#pragma unroll
        for (int nt = 0; nt < 4; nt++) {
            const int cc = bn + wn + nt * 8 + c2;
            if (cc < N) {
                const float b0 = bias[cc], b1 = bias[cc + 1];
#pragma unroll
                for (int hh = 0; hh < 2; hh++) {
                    const int rr = r0 + hh * 8;
                    if (rr < M) {
                        float ox = acc[mt][nt][hh * 2 + 0] + b0;
                        float oy = acc[mt][nt][hh * 2 + 1] + b1;
                        if (RELU) { ox = fmaxf(ox, 0.f); oy = fmaxf(oy, 0.f); }
                        if (OUT_HALF) {
                            *(uint32_t*)&Ch[(size_t)rr * N + cc] = packh2(ox, oy);
                        } else {
                            *(float2*)&Cf[(size_t)rr * N + cc] = make_float2(ox, oy);
                        }
                    }
                }
            }
        }
    }
}

// ---------------- fused prologue: src/q conversion + all weight pairs + bias ----------------
__device__ __forceinline__ void cvtpair(const float* __restrict__ W, uint32_t* __restrict__ Wp,
                                        int i, int N, int NP, int coloff) {
    const int kp = i / N, n = i - kp * N;
    Wp[(size_t)kp * NP + coloff + n] =
        packh2(W[(size_t)(2 * kp) * N + n], W[(size_t)(2 * kp + 1) * N + n]);
}

__global__ __launch_bounds__(256)
void conv_all(const float2* __restrict__ src, const float2* __restrict__ pos,
              uint32_t* __restrict__ src16, uint32_t* __restrict__ q16, int n2,
              const float* __restrict__ wv,  const float* __restrict__ wo,
              const float* __restrict__ wa,  const float* __restrict__ wout,
              const float* __restrict__ w1,  const float* __restrict__ w2,
              const float* __restrict__ bo,  const float* __restrict__ ba,
              uint32_t* __restrict__ wvp,    uint32_t* __restrict__ woap,
              uint32_t* __restrict__ woutp,  uint32_t* __restrict__ w1p,
              uint32_t* __restrict__ w2p,    float* __restrict__ boa)
{
    int i = blockIdx.x * 256 + threadIdx.x;
    if (i < n2) {
        float2 s = src[i], p = pos[i];
        src16[i] = packh2(s.x, s.y);
        q16[i]   = packh2(s.x + p.x, s.y + p.y);
        return;
    }
    i -= n2;
    if (i < 32768)  { cvtpair(wv,   wvp,   i, 256,  256,  0);   return; }  i -= 32768;
    if (i < 40960)  { cvtpair(wo,   woap,  i, 320,  480,  0);   return; }  i -= 40960;
    if (i < 20480)  { cvtpair(wa,   woap,  i, 160,  480,  320); return; }  i -= 20480;
    if (i < 32768)  { cvtpair(wout, woutp, i, 256,  256,  0);   return; }  i -= 32768;
    if (i < 262144) { cvtpair(w1,   w1p,   i, 2048, 2048, 0);   return; }  i -= 262144;
    if (i < 262144) { cvtpair(w2,   w2p,   i, 256,  256,  0);   return; }  i -= 262144;
    if (i < 480)    { boa[i] = (i < 320) ? bo[i] : ba[i - 320]; }
}

// ---------------- deformable sampling: two-phase, fp16 value gathers ----------------
__global__ __launch_bounds__(64)
void sample_kernel(const uint32_t* __restrict__ val16,  // half2 [B*L][128]
                   const float* __restrict__ ref,
                   const float* __restrict__ oa,        // [B*L][480] off|log
                   uint32_t* __restrict__ acc16)        // half2 [B*L][128]
{
    const int q = blockIdx.x;
    const int b = q / L_Q;
    const int t = threadIdx.x;

    __shared__ float  s_off[320];
    __shared__ float  s_log[160];
    __shared__ float  s_ref[10];
    __shared__ float  s_m[8], s_inv[8];
    __shared__ float4 s_cw[160];
    __shared__ int4   s_id[160];

    const float* row = oa + (size_t)q * 480;
#pragma unroll
    for (int i = t; i < 320; i += 64) s_off[i] = row[i];
#pragma unroll
    for (int i = t; i < 160; i += 64) s_log[i] = row[320 + i];
    if (t < 10) s_ref[t] = ref[(size_t)q * 10 + t];
    __syncthreads();

    // phase 1a: per-head softmax stats
    if (t < 8) {
        float m = -1e30f;
#pragma unroll
        for (int p = 0; p < 20; p++) m = fmaxf(m, s_log[t * 20 + p]);
        float ss = 0.f;
#pragma unroll
        for (int p = 0; p < 20; p++) ss += __expf(s_log[t * 20 + p] - m);
        s_m[t] = m; s_inv[t] = 1.0f / ss;
    }
    __syncthreads();

    // phase 1b: combined corner weights + half2-word offsets (160 pairs)
#pragma unroll
    for (int i = t; i < 160; i += 64) {
        const int h  = i / 20;
        const int lp = i - h * 20;
        const int l  = lp >> 2;
        const int Ws = c_HW[l];
        const int base = c_start[l];

        const float w = __expf(s_log[i] - s_m[h]) * s_inv[h];
        const float ox = s_off[h * 40 + lp * 2 + 0];
        const float oy = s_off[h * 40 + lp * 2 + 1];
        const float rx = s_ref[l * 2 + 0];
        const float ry = s_ref[l * 2 + 1];

        const float locx = rx + ox / (float)Ws;
        const float locy = ry + oy / (float)Ws;
        const float px = locx * (float)Ws - 0.5f;
        const float py = locy * (float)Ws - 0.5f;

        const float x0f = floorf(px), y0f = floorf(py);
        const float lx = px - x0f, ly = py - y0f;
        const int x0 = (int)x0f, y0 = (int)y0f;
        const int x1 = x0 + 1,  y1 = y0 + 1;

        const bool vx0 = (x0 >= 0) & (x0 < Ws);
        const bool vx1 = (x1 >= 0) & (x1 < Ws);
        const bool vy0 = (y0 >= 0) & (y0 < Ws);
        const bool vy1 = (y1 >= 0) & (y1 < Ws);

        const float wx0 = 1.f - lx, wx1 = lx;
        const float wy0 = 1.f - ly, wy1 = ly;

        float4 cw; int4 id;
        const bool c00 = vx0 & vy0, c10 = vx1 & vy0, c01 = vx0 & vy1, c11 = vx1 & vy1;
        cw.x = c00 ? w * wx0 * wy0 : 0.f;  id.x = c00 ? (base + y0 * Ws + x0) * 128 : 0;
        cw.y = c10 ? w * wx1 * wy0 : 0.f;  id.y = c10 ? (base + y0 * Ws + x1) * 128 : 0;
        cw.z = c01 ? w * wx0 * wy1 : 0.f;  id.z = c01 ? (base + y1 * Ws + x0) * 128 : 0;
        cw.w = c11 ? w * wx1 * wy1 : 0.f;  id.w = c11 ? (base + y1 * Ws + x1) * 128 : 0;
        s_cw[i] = cw; s_id[i] = id;
    }
    __syncthreads();

    // phase 2: fp16 gathers (uint2 = 4 channels)
    const int h  = t >> 3;
    const int cg = (t & 7) * 2;            // half2-word offset within head
    const uint32_t* vb = val16 + (size_t)b * L_Q * 128 + h * 16 + cg;

    float4 a0 = make_float4(0.f, 0.f, 0.f, 0.f);
    float4 a1 = a0, a2 = a0, a3 = a0;

#pragma unroll 5
    for (int p = 0; p < 20; p++) {
        const float4 cw = s_cw[h * 20 + p];
        const int4   id = s_id[h * 20 + p];
        uint2 u; float2 v0, v1;
        u = *(const uint2*)(vb + id.x);
        v0 = __half22float2(*(__half2*)&u.x); v1 = __half22float2(*(__half2*)&u.y);
        a0.x = fmaf(cw.x, v0.x, a0.x); a0.y = fmaf(cw.x, v0.y, a0.y);
        a0.z = fmaf(cw.x, v1.x, a0.z); a0.w = fmaf(cw.x, v1.y, a0.w);
        u = *(const uint2*)(vb + id.y);
        v0 = __half22float2(*(__half2*)&u.x); v1 = __half22float2(*(__half2*)&u.y);
        a1.x = fmaf(cw.y, v0.x, a1.x); a1.y = fmaf(cw.y, v0.y, a1.y);
        a1.z = fmaf(cw.y, v1.x, a1.z); a1.w = fmaf(cw.y, v1.y, a1.w);
        u = *(const uint2*)(vb + id.z);
        v0 = __half22float2(*(__half2*)&u.x); v1 = __half22float2(*(__half2*)&u.y);
        a2.x = fmaf(cw.z, v0.x, a2.x); a2.y = fmaf(cw.z, v0.y, a2.y);
        a2.z = fmaf(cw.z, v1.x, a2.z); a2.w = fmaf(cw.z, v1.y, a2.w);
        u = *(const uint2*)(vb + id.w);
        v0 = __half22float2(*(__half2*)&u.x); v1 = __half22float2(*(__half2*)&u.y);
        a3.x = fmaf(cw.w, v0.x, a3.x); a3.y = fmaf(cw.w, v0.y, a3.y);
        a3.z = fmaf(cw.w, v1.x, a3.z); a3.w = fmaf(cw.w, v1.y, a3.w);
    }
    float4 a;
    a.x = (a0.x + a1.x) + (a2.x + a3.x);
    a.y = (a0.y + a1.y) + (a2.y + a3.y);
    a.z = (a0.z + a1.z) + (a2.z + a3.z);
    a.w = (a0.w + a1.w) + (a2.w + a3.w);

    uint2 o;
    o.x = packh2(a.x, a.y);
    o.y = packh2(a.z, a.w);
    *(uint2*)&acc16[(size_t)q * 128 + h * 16 + cg] = o;
}

// ---------------- fused add + layernorm (optional fp16 copy) ----------------
template<bool STORE_HALF>
__global__ __launch_bounds__(256)
void add_ln_kernel(const float* __restrict__ a, const float* __restrict__ b,
                   const float* __restrict__ g, const float* __restrict__ be,
                   float* __restrict__ out, uint32_t* __restrict__ out16, int M)
{
    const int warp = threadIdx.x >> 5;
    const int lane = threadIdx.x & 31;
    const int row  = blockIdx.x * 8 + warp;
    if (row >= M) return;

    const float* ar = a + (size_t)row * 256;
    const float* br = b + (size_t)row * 256;

    float4 v0 = *(const float4*)(ar + lane * 4);
    float4 v1 = *(const float4*)(ar + 128 + lane * 4);
    float4 w0 = *(const float4*)(br + lane * 4);
    float4 w1 = *(const float4*)(br + 128 + lane * 4);

    float v[8];
    v[0] = v0.x + w0.x; v[1] = v0.y + w0.y; v[2] = v0.z + w0.z; v[3] = v0.w + w0.w;
    v[4] = v1.x + w1.x; v[5] = v1.y + w1.y; v[6] = v1.z + w1.z; v[7] = v1.w + w1.w;

    float s = 0.f, sq = 0.f;
#pragma unroll
    for (int i = 0; i < 8; i++) { s += v[i]; sq = fmaf(v[i], v[i], sq); }
#pragma unroll
    for (int o = 16; o; o >>= 1) {
        s  += __shfl_xor_sync(0xffffffffu, s,  o);
        sq += __shfl_xor_sync(0xffffffffu, sq, o);
    }
    const float mean = s * (1.f / 256.f);
    const float var  = sq * (1.f / 256.f) - mean * mean;
    const float inv  = rsqrtf(var + 1e-5f);

    float* orow = out + (size_t)row * 256;
#pragma unroll
    for (int half = 0; half < 2; half++) {
        const int c = half * 128 + lane * 4;
        float4 o;
        float* vv = v + half * 4;
        o.x = (vv[0] - mean) * inv * g[c + 0] + be[c + 0];
        o.y = (vv[1] - mean) * inv * g[c + 1] + be[c + 1];
        o.z = (vv[2] - mean) * inv * g[c + 2] + be[c + 2];
        o.w = (vv[3] - mean) * inv * g[c + 3] + be[c + 3];
        *(float4*)&orow[c] = o;
        if (STORE_HALF) {
            uint2 u;
            u.x = packh2(o.x, o.y);
            u.y = packh2(o.z, o.w);
            *(uint2*)&out16[(size_t)row * 128 + (c >> 1)] = u;
        }
    }
}

// ---------------- launch ----------------
extern "C" void kernel_launch(void* const* d_in, const int* in_sizes, int n_in,
                              void* d_out, int out_size)
{
    const float* src  = (const float*)d_in[0];
    const float* pos  = (const float*)d_in[1];
    const float* ref  = (const float*)d_in[2];
    const float* wv   = (const float*)d_in[3];
    const float* bv   = (const float*)d_in[4];
    const float* wo   = (const float*)d_in[5];
    const float* bo   = (const float*)d_in[6];
    const float* wa   = (const float*)d_in[7];
    const float* ba   = (const float*)d_in[8];
    const float* wout = (const float*)d_in[9];
    const float* bout = (const float*)d_in[10];
    const float* ln1g = (const float*)d_in[11];
    const float* ln1b = (const float*)d_in[12];
    const float* w1   = (const float*)d_in[13];
    const float* b1   = (const float*)d_in[14];
    const float* w2   = (const float*)d_in[15];
    const float* b2   = (const float*)d_in[16];
    const float* ln2g = (const float*)d_in[17];
    const float* ln2b = (const float*)d_in[18];
    float* out = (float*)d_out;

    const int M  = in_sizes[0] / CDIM;       // 26686
    const int mt = (M + 127) / 128;          // 209

    float *oap, *src2, *xp, *yp, *boap;
    uint32_t *src16, *q16, *val16, *acc16, *x16, *h16;
    uint32_t *wvp, *woap, *woutp, *w1p, *w2p;
    cudaGetSymbolAddress((void**)&oap,   g_oa);
    cudaGetSymbolAddress((void**)&src2,  g_src2);
    cudaGetSymbolAddress((void**)&xp,    g_x);
    cudaGetSymbolAddress((void**)&yp,    g_y);
    cudaGetSymbolAddress((void**)&src16, g_src16);
    cudaGetSymbolAddress((void**)&q16,   g_q16);
    cudaGetSymbolAddress((void**)&val16, g_val16);
    cudaGetSymbolAddress((void**)&acc16, g_acc16);
    cudaGetSymbolAddress((void**)&x16,   g_x16);
    cudaGetSymbolAddress((void**)&h16,   g_h16);
    cudaGetSymbolAddress((void**)&wvp,   g_wvp);
    cudaGetSymbolAddress((void**)&woap,  g_woap);
    cudaGetSymbolAddress((void**)&woutp, g_woutp);
    cudaGetSymbolAddress((void**)&w1p,   g_w1p);
    cudaGetSymbolAddress((void**)&w2p,   g_w2p);
    cudaGetSymbolAddress((void**)&boap,  g_boa);

    cudaFuncSetAttribute(gemm_h<false, false>, cudaFuncAttributeMaxDynamicSharedMemorySize, SMEM_GEMM);
    cudaFuncSetAttribute(gemm_h<false, true>,  cudaFuncAttributeMaxDynamicSharedMemorySize, SMEM_GEMM);
    cudaFuncSetAttribute(gemm_h<true,  true>,  cudaFuncAttributeMaxDynamicSharedMemorySize, SMEM_GEMM);

    // 0) fused prologue: activations + all weights + bias concat in ONE launch
    const int n2 = M * 128;
    const int total = n2 + 651264 + 480;
    conv_all<<<(total + 255) / 256, 256>>>(
        (const float2*)src, (const float2*)pos, src16, q16, n2,
        wv, wo, wa, wout, w1, w2, bo, ba,
        wvp, woap, woutp, w1p, w2p, boap);

    // 1) value = src @ wv + bv -> fp16
    gemm_h<false, true><<<dim3(2, mt), 256, SMEM_GEMM>>>((const __half*)src16, wvp, bv, val16, M, 256, 256);
    // 2+3) [offsets|logits] = q @ [wo|wa] + [bo|ba]
    gemm_h<false, false><<<dim3(4, mt), 256, SMEM_GEMM>>>((const __half*)q16, woap, boap, oap, M, 480, 256);
    // 4) deformable sampling -> acc16
    sample_kernel<<<M, 64>>>(val16, ref, oap, acc16);
    // 5) src2 = acc @ wout + bout
    gemm_h<false, false><<<dim3(2, mt), 256, SMEM_GEMM>>>((const __half*)acc16, woutp, bout, src2, M, 256, 256);
    // 6) x = LN(src + src2)  (+ fp16 copy)
    add_ln_kernel<true><<<(M + 7) / 8, 256>>>(src, src2, ln1g, ln1b, xp, x16, M);
    // 7) h = relu(x @ w1 + b1) -> fp16
    gemm_h<true, true><<<dim3(16, mt), 256, SMEM_GEMM>>>((const __half*)x16, w1p, b1, h16, M, 2048, 256);
    // 8) y = h @ w2 + b2
    gemm_h<false, false><<<dim3(2, mt), 256, SMEM_GEMM>>>((const __half*)h16, w2p, b2, yp, M, 256, 2048);
    // 9) out = LN(x + y)
    add_ln_kernel<false><<<(M + 7) / 8, 256>>>(xp, yp, ln2g, ln2b, out, nullptr, M);
}